// round 10
// baseline (speedup 1.0000x reference)
#include <cuda_runtime.h>
#include <cstdint>
#include <cstddef>

// Sparsemax (alpha=2). One 2-CTA cluster per row; each CTA holds its 62.5KB
// half-row entirely in shared memory => DRAM traffic is exactly 1 read +
// 1 write, with NO L2 re-reads (the R4/R9 L2-thrash failure mode is gone).
// Cross-CTA exchange (row max, candidate lists, fallback partial sums) goes
// through DSMEM + cluster barriers.
// Candidate set {x > rowmax-1} is exact for the reference bisection: every
// iterate tau_m > rowmax-1, so all other elements contribute 0 to f(tau).
// tau: closed-form sorted-threshold rule for K<=32 (typical K ~ 8-30; sorted
// => both CTAs compute bit-identical tau), warp bisection over the merged
// list for K<=1024, cross-CTA block bisection as the overflow fallback.

#define SPM_D   32000
#define HALF_F  16000            // floats per CTA half
#define HALF4   4000             // float4 per CTA half (62.5KB)
#define SPM_NT  384
#define SPM_NW  (SPM_NT / 32)    // 12 warps
#define N_IT    11               // ceil(4000/384); last iter partial
#define FCAP    512

#define NEG_INF (-3.402823466e38f)
#define FULL    0xffffffffu

__device__ __forceinline__ float warp_max(float v) {
#pragma unroll
    for (int o = 16; o; o >>= 1) v = fmaxf(v, __shfl_xor_sync(FULL, v, o));
    return v;
}
__device__ __forceinline__ float warp_sum(float v) {
#pragma unroll
    for (int o = 16; o; o >>= 1) v += __shfl_xor_sync(FULL, v, o);
    return v;
}
__device__ __forceinline__ uint32_t smem_u32(const void* p) {
    uint32_t a;
    asm("{ .reg .u64 t; cvta.to.shared.u64 t, %1; cvt.u32.u64 %0, t; }"
        : "=r"(a) : "l"(p));
    return a;
}
__device__ __forceinline__ uint32_t mapa_peer(uint32_t laddr, uint32_t rank) {
    uint32_t r;
    asm("mapa.shared::cluster.u32 %0, %1, %2;" : "=r"(r) : "r"(laddr), "r"(rank));
    return r;
}
__device__ __forceinline__ void dsmem_st_f32(uint32_t a, float v) {
    asm volatile("st.shared::cluster.f32 [%0], %1;" :: "r"(a), "f"(v) : "memory");
}
__device__ __forceinline__ float dsmem_ld_f32(uint32_t a) {
    float v;
    asm volatile("ld.shared::cluster.f32 %0, [%1];" : "=f"(v) : "r"(a) : "memory");
    return v;
}
__device__ __forceinline__ int dsmem_ld_s32(uint32_t a) {
    int v;
    asm volatile("ld.shared::cluster.s32 %0, [%1];" : "=r"(v) : "r"(a) : "memory");
    return v;
}
__device__ __forceinline__ void cluster_sync() {
    asm volatile("barrier.cluster.arrive.aligned;" ::: "memory");
    asm volatile("barrier.cluster.wait.aligned;" ::: "memory");
}

extern __shared__ float4 s_x4[];   // HALF4 float4 = 62.5KB dynamic

__global__ __cluster_dims__(2, 1, 1) __launch_bounds__(SPM_NT, 3)
void spm_kernel(const float* __restrict__ X, float* __restrict__ Y) {
    __shared__ float s_filt[2 * FCAP];
    __shared__ float s_wmax[SPM_NW];
    __shared__ float s_r[SPM_NW];
    __shared__ int   s_K;
    __shared__ float s_peer_max;
    __shared__ float s_mail[2];
    __shared__ float s_tau, s_inv;

    const int tid  = threadIdx.x;
    const int lane = tid & 31;
    const int wid  = tid >> 5;
    const uint32_t rank = blockIdx.x & 1;     // cluster cta rank
    const uint32_t peer = rank ^ 1;
    const long row = blockIdx.x >> 1;

    const float4* __restrict__ x4 = reinterpret_cast<const float4*>(
        X + row * (long)SPM_D + (long)rank * HALF_F);
    float4* __restrict__ y4 = reinterpret_cast<float4*>(
        Y + row * (long)SPM_D + (long)rank * HALF_F);

    if (tid == 0) s_K = 0;

    // ---- P1: load half into smem; private per-thread max ----
    float mxc = NEG_INF;
#pragma unroll
    for (int j = 0; j < N_IT; ++j) {
        const int i = j * SPM_NT + tid;
        if (i < HALF4) {
            float4 v = __ldcs(&x4[i]);
            s_x4[i] = v;
            mxc = fmaxf(mxc, fmaxf(fmaxf(v.x, v.y), fmaxf(v.z, v.w)));
        }
    }
    float mw = warp_max(mxc);
    if (lane == 0) s_wmax[wid] = mw;
    __syncthreads();
    float mm = (lane < SPM_NW) ? s_wmax[lane] : NEG_INF;
    const float halfmax = warp_max(mm);       // my half's max (all warps)

    // ---- exchange halves' maxima ----
    if (tid == 0)
        dsmem_st_f32(mapa_peer(smem_u32(&s_peer_max), peer), halfmax);
    cluster_sync();                            // also orders s_K reset
    const float mxv   = fmaxf(halfmax, s_peer_max);
    const float thrF  = mxv - 1.0f;
    const float inv_d = 1.0f / (float)SPM_D;

    // ---- P2: exact local gather via private-max guard (rare path) ----
    if (mxc > thrF) {
#pragma unroll
        for (int j = 0; j < N_IT; ++j) {
            const int i = j * SPM_NT + tid;
            if (i < HALF4) {
                float4 v = s_x4[i];
                if (v.x > thrF) { int p = atomicAdd(&s_K, 1); if (p < FCAP) s_filt[p] = v.x; }
                if (v.y > thrF) { int p = atomicAdd(&s_K, 1); if (p < FCAP) s_filt[p] = v.y; }
                if (v.z > thrF) { int p = atomicAdd(&s_K, 1); if (p < FCAP) s_filt[p] = v.z; }
                if (v.w > thrF) { int p = atomicAdd(&s_K, 1); if (p < FCAP) s_filt[p] = v.w; }
            }
        }
    }
    cluster_sync();                            // publish candidates + counts

    const int Kl = s_K;
    const int Kp = dsmem_ld_s32(mapa_peer(smem_u32(&s_K), peer));
    const int Kt = Kl + Kp;                    // >= 1 always
    const bool need_full = (Kl > FCAP) || (Kp > FCAP);

    float tau = 0.0f, inv = 1.0f;
    const uint32_t peer_filt0 = mapa_peer(smem_u32(&s_filt[0]), peer);

    if (!need_full && Kt <= 32) {
        // ---- Closed-form threshold, redundant per-warp ----
        float z = NEG_INF;
        if (lane < Kl)      z = s_filt[lane];
        else if (lane < Kt) z = dsmem_ld_f32(peer_filt0 + 4u * (lane - Kl));
        // bitonic sort, descending => identical tau in both CTAs
#pragma unroll
        for (int kk = 2; kk <= 32; kk <<= 1) {
#pragma unroll
            for (int j = kk >> 1; j > 0; j >>= 1) {
                float o = __shfl_xor_sync(FULL, z, j);
                bool lower   = (lane & j) == 0;
                bool descBlk = (lane & kk) == 0;
                z = (lower == descBlk) ? fmaxf(z, o) : fminf(z, o);
            }
        }
        float S = z;
#pragma unroll
        for (int o = 1; o < 32; o <<= 1) {
            float t = __shfl_up_sync(FULL, S, o);
            if (lane >= o) S += t;
        }
        float kf = (float)(lane + 1);
        unsigned bal = __ballot_sync(FULL, fmaf(kf, z, 1.0f) > S);
        int h = 31 - __clz(bal);               // lane 0 always qualifies
        tau = __shfl_sync(FULL, (S - 1.0f) / kf, h);
        float s = warp_sum(fmaxf(z - tau, 0.0f));
        inv = 1.0f / s;
    } else if (!need_full) {
        // ---- Merge peer list, warp-0 reference bisection ----
        for (int i = tid; i < Kp; i += SPM_NT)
            s_filt[Kl + i] = dsmem_ld_f32(peer_filt0 + 4u * i);
        __syncthreads();
        if (wid == 0) {
            float tlo = thrF;
            float dm  = (mxv - inv_d) - tlo;
            float a = 0.0f;
            for (int i = lane; i < Kt; i += 32)
                a += fmaxf(s_filt[i] - tlo, 0.0f);
            const float flo = warp_sum(a) - 1.0f;
            float tm = tlo, fm = flo;
            for (int it = 0; it < 50; ++it) {
                dm *= 0.5f;
                tm = tlo + dm;
                float s = 0.0f;
                for (int i = lane; i < Kt; i += 32)
                    s += fmaxf(s_filt[i] - tm, 0.0f);
                fm = warp_sum(s) - 1.0f;
                if (fm * flo >= 0.0f) tlo = tm;
            }
            if (lane == 0) { s_tau = tm; s_inv = 1.0f / (fm + 1.0f); }
        }
        __syncthreads();
        tau = s_tau; inv = s_inv;
    } else {
        // ---- Overflow fallback: cross-CTA block bisection (never on this
        //      data; correctness only). One cluster.sync per exchange,
        //      2 alternating mailbox slots. ----
        float tlo = thrF;
        float dm  = (mxv - inv_d) - tlo;

        // local partial of f(tlo), redundant per warp
        float a = 0.0f;
        for (int i = tid; i < HALF4; i += SPM_NT) {
            float4 v = s_x4[i];
            a += fmaxf(v.x - tlo, 0.0f) + fmaxf(v.y - tlo, 0.0f) +
                 fmaxf(v.z - tlo, 0.0f) + fmaxf(v.w - tlo, 0.0f);
        }
        a = warp_sum(a);
        if (lane == 0) s_r[wid] = a;
        __syncthreads();
        float ra = (lane < SPM_NW) ? s_r[lane] : 0.0f;
        float loc = warp_sum(ra);
        __syncthreads();
        if (tid == 0)
            dsmem_st_f32(mapa_peer(smem_u32(&s_mail[0]), peer), loc);
        cluster_sync();
        const float flo = (loc + s_mail[0]) - 1.0f;

        float tm = tlo, fm = flo;
        for (int it = 0; it < 50; ++it) {
            dm *= 0.5f;
            tm = tlo + dm;
            float s = 0.0f;
            for (int i = tid; i < HALF4; i += SPM_NT) {
                float4 v = s_x4[i];
                s += fmaxf(v.x - tm, 0.0f) + fmaxf(v.y - tm, 0.0f) +
                     fmaxf(v.z - tm, 0.0f) + fmaxf(v.w - tm, 0.0f);
            }
            s = warp_sum(s);
            if (lane == 0) s_r[wid] = s;
            __syncthreads();
            float rr = (lane < SPM_NW) ? s_r[lane] : 0.0f;
            float l2 = warp_sum(rr);
            __syncthreads();
            const int slot = (it + 1) & 1;
            if (tid == 0)
                dsmem_st_f32(mapa_peer(smem_u32(&s_mail[slot]), peer), l2);
            cluster_sync();
            fm = (l2 + s_mail[slot]) - 1.0f;
            if (fm * flo >= 0.0f) tlo = tm;
        }
        tau = tm;
        inv = 1.0f / (fm + 1.0f);
    }

    cluster_sync();   // no peer-smem access after this; safe to diverge/exit

    // ---- P3: write half from smem (streaming stores) ----
#pragma unroll
    for (int j = 0; j < N_IT; ++j) {
        const int i = j * SPM_NT + tid;
        if (i < HALF4) {
            float4 v = s_x4[i];
            float4 r;
            r.x = fmaxf(v.x - tau, 0.0f) * inv;
            r.y = fmaxf(v.y - tau, 0.0f) * inv;
            r.z = fmaxf(v.z - tau, 0.0f) * inv;
            r.w = fmaxf(v.w - tau, 0.0f) * inv;
            __stcs(&y4[i], r);
        }
    }
}

extern "C" void kernel_launch(void* const* d_in, const int* in_sizes, int n_in,
                              void* d_out, int out_size) {
    const float* X = (const float*)d_in[0];
    float* Y       = (float*)d_out;
    const int rows = in_sizes[0] / SPM_D;
    const int shmem = HALF4 * sizeof(float4);   // 64000 B dynamic

    cudaFuncSetAttribute(spm_kernel,
                         cudaFuncAttributeMaxDynamicSharedMemorySize, shmem);
    cudaFuncSetAttribute(spm_kernel,
                         cudaFuncAttributePreferredSharedMemoryCarveout,
                         cudaSharedmemCarveoutMaxShared);
    spm_kernel<<<rows * 2, SPM_NT, shmem>>>(X, Y);
}

// round 11
// speedup vs baseline: 1.2632x; 1.2632x over previous
#include <cuda_runtime.h>
#include <cstddef>

// Sparsemax (alpha=2), read-once + zero-fill + sparse scatter.
// KEY FACT: every reference bisection iterate tau_m > rowmax-1, so every
// element x <= rowmax-1 yields EXACTLY 0 in the output (max(x-tau_m,0)=0,
// 0/sum=0). Only the K ~ 8-30 candidates {x > rowmax-1} can be nonzero.
// Therefore:
//   P1: single fused stream: read x (__ldcs) + write 0 to y (__stcs) + track
//       per-thread private max. Read+write both saturate DRAM; nothing needs
//       L2 or smem residency -> 6 CTAs/SM of independent bubble-hiding.
//   P2: threads whose private max > rowmax-1 re-read their own elements
//       (~10 threads/CTA, ~32KB/row) and gather (val,idx) into smem.
//   tau: closed-form sorted-threshold rule for K<=32 (computed redundantly
//       in every warp), warp-0 reference bisection for K<=FCAP, full-row
//       gmem bisection as overflow fallback.
//   P3: scatter the K nonzero outputs (overwrites the zeros; WAW across
//       threads ordered by the intervening __syncthreads).

#define SPM_D   32000
#define SPM_D4  (SPM_D / 4)      // 8000 float4
#define SPM_NT  320
#define SPM_NW  (SPM_NT / 32)    // 10 warps
#define N_IT    25               // 8000 / 320 exact
#define FCAP    512

#define NEG_INF (-3.402823466e38f)
#define FULL    0xffffffffu

__device__ __forceinline__ float warp_max(float v) {
#pragma unroll
    for (int o = 16; o; o >>= 1) v = fmaxf(v, __shfl_xor_sync(FULL, v, o));
    return v;
}
__device__ __forceinline__ float warp_sum(float v) {
#pragma unroll
    for (int o = 16; o; o >>= 1) v += __shfl_xor_sync(FULL, v, o);
    return v;
}

__global__ __launch_bounds__(SPM_NT, 6)
void spm_kernel(const float* __restrict__ X, float* __restrict__ Y) {
    __shared__ float s_val[FCAP];
    __shared__ int   s_idx[FCAP];
    __shared__ float s_wmax[SPM_NW];
    __shared__ float s_r[SPM_NW];
    __shared__ int   s_K;
    __shared__ float s_tau, s_inv;

    const int tid  = threadIdx.x;
    const int lane = tid & 31;
    const int wid  = tid >> 5;
    const long row = blockIdx.x;

    const float4* __restrict__ x4 =
        reinterpret_cast<const float4*>(X + row * (long)SPM_D);
    float4* __restrict__ y4 =
        reinterpret_cast<float4*>(Y + row * (long)SPM_D);

    if (tid == 0) s_K = 0;

    // ---- P1: fused read-stream + zero-fill + private max ----
    const float4 zero4 = make_float4(0.0f, 0.0f, 0.0f, 0.0f);
    float mxc = NEG_INF;
#pragma unroll 5
    for (int j = 0; j < N_IT; ++j) {
        const int i = j * SPM_NT + tid;
        float4 v = __ldcs(&x4[i]);
        __stcs(&y4[i], zero4);
        mxc = fmaxf(mxc, fmaxf(fmaxf(v.x, v.y), fmaxf(v.z, v.w)));
    }
    float mw = warp_max(mxc);
    if (lane == 0) s_wmax[wid] = mw;
    __syncthreads();                           // barrier 1 (orders s_K too)

    float mm = (lane < SPM_NW) ? s_wmax[lane] : NEG_INF;
    const float mxv   = warp_max(mm);          // block max, redundant per warp
    const float thrF  = mxv - 1.0f;
    const float inv_d = 1.0f / (float)SPM_D;

    // ---- P2: rare threads re-read own elements, gather (val, idx) ----
    if (mxc > thrF) {
#pragma unroll 5
        for (int j = 0; j < N_IT; ++j) {
            const int i = j * SPM_NT + tid;
            float4 v = __ldcg(&x4[i]);
            if (v.x > thrF) { int p = atomicAdd(&s_K, 1); if (p < FCAP) { s_val[p] = v.x; s_idx[p] = 4*i+0; } }
            if (v.y > thrF) { int p = atomicAdd(&s_K, 1); if (p < FCAP) { s_val[p] = v.y; s_idx[p] = 4*i+1; } }
            if (v.z > thrF) { int p = atomicAdd(&s_K, 1); if (p < FCAP) { s_val[p] = v.z; s_idx[p] = 4*i+2; } }
            if (v.w > thrF) { int p = atomicAdd(&s_K, 1); if (p < FCAP) { s_val[p] = v.w; s_idx[p] = 4*i+3; } }
        }
    }
    __syncthreads();                           // barrier 2
    const int K = s_K;                         // uniform; K >= 1 always

    float tau = 0.0f, inv = 1.0f;

    if (K <= 32) {
        // ---- Closed-form threshold, redundant per-warp (no barrier) ----
        float z = (lane < K) ? s_val[lane] : NEG_INF;
        // bitonic sort, descending
#pragma unroll
        for (int kk = 2; kk <= 32; kk <<= 1) {
#pragma unroll
            for (int j = kk >> 1; j > 0; j >>= 1) {
                float o = __shfl_xor_sync(FULL, z, j);
                bool lower   = (lane & j) == 0;
                bool descBlk = (lane & kk) == 0;
                z = (lower == descBlk) ? fmaxf(z, o) : fminf(z, o);
            }
        }
        // inclusive prefix sum
        float S = z;
#pragma unroll
        for (int o = 1; o < 32; o <<= 1) {
            float t = __shfl_up_sync(FULL, S, o);
            if (lane >= o) S += t;
        }
        float kf = (float)(lane + 1);
        unsigned bal = __ballot_sync(FULL, fmaf(kf, z, 1.0f) > S);
        int h = 31 - __clz(bal);               // lane 0 always qualifies
        tau = __shfl_sync(FULL, (S - 1.0f) / kf, h);
        float s = warp_sum(fmaxf(z - tau, 0.0f));
        inv = 1.0f / s;

        // ---- P3: sparse scatter of the K nonzero outputs ----
        if (tid < K)
            Y[row * (long)SPM_D + s_idx[tid]] =
                fmaxf(s_val[tid] - tau, 0.0f) * inv;
    } else if (K <= FCAP) {
        // ---- Reference bisection over candidates (warp 0) ----
        if (wid == 0) {
            float tlo = thrF;
            float dm  = (mxv - inv_d) - tlo;
            float a = 0.0f;
            for (int i = lane; i < K; i += 32)
                a += fmaxf(s_val[i] - tlo, 0.0f);
            const float flo = warp_sum(a) - 1.0f;
            float tm = tlo, fm = flo;
            for (int it = 0; it < 50; ++it) {
                dm *= 0.5f;
                tm = tlo + dm;
                float s = 0.0f;
                for (int i = lane; i < K; i += 32)
                    s += fmaxf(s_val[i] - tm, 0.0f);
                fm = warp_sum(s) - 1.0f;
                if (fm * flo >= 0.0f) tlo = tm;
            }
            if (lane == 0) { s_tau = tm; s_inv = 1.0f / (fm + 1.0f); }
        }
        __syncthreads();
        tau = s_tau; inv = s_inv;

        for (int p = tid; p < K; p += SPM_NT)
            Y[row * (long)SPM_D + s_idx[p]] =
                fmaxf(s_val[p] - tau, 0.0f) * inv;
    } else {
        // ---- Overflow fallback (correctness only): full-row bisection ----
        float tlo = thrF;
        float dm  = (mxv - inv_d) - tlo;

        float a = 0.0f;
        for (int i = tid; i < SPM_D4; i += SPM_NT) {
            float4 v = __ldcg(&x4[i]);
            a += fmaxf(v.x - tlo, 0.0f) + fmaxf(v.y - tlo, 0.0f) +
                 fmaxf(v.z - tlo, 0.0f) + fmaxf(v.w - tlo, 0.0f);
        }
        a = warp_sum(a);
        if (lane == 0) s_r[wid] = a;
        __syncthreads();
        float r0 = (lane < SPM_NW) ? s_r[lane] : 0.0f;
        const float flo = warp_sum(r0) - 1.0f;

        float tm = tlo, fm = flo;
        for (int it = 0; it < 50; ++it) {
            dm *= 0.5f;
            tm = tlo + dm;
            float s = 0.0f;
            for (int i = tid; i < SPM_D4; i += SPM_NT) {
                float4 v = __ldcg(&x4[i]);
                s += fmaxf(v.x - tm, 0.0f) + fmaxf(v.y - tm, 0.0f) +
                     fmaxf(v.z - tm, 0.0f) + fmaxf(v.w - tm, 0.0f);
            }
            s = warp_sum(s);
            __syncthreads();
            if (lane == 0) s_r[wid] = s;
            __syncthreads();
            float rr = (lane < SPM_NW) ? s_r[lane] : 0.0f;
            fm = warp_sum(rr) - 1.0f;
            if (fm * flo >= 0.0f) tlo = tm;
        }
        tau = tm;
        inv = 1.0f / (fm + 1.0f);

        // scatter: owning threads rescan and write elements above thrF
        // (elements in (thrF, tau] write 0 over 0 -- harmless)
        if (mxc > thrF) {
#pragma unroll 5
            for (int j = 0; j < N_IT; ++j) {
                const int i = j * SPM_NT + tid;
                float4 v = __ldcg(&x4[i]);
                if (v.x > thrF) Y[row*(long)SPM_D + 4*i+0] = fmaxf(v.x - tau, 0.0f) * inv;
                if (v.y > thrF) Y[row*(long)SPM_D + 4*i+1] = fmaxf(v.y - tau, 0.0f) * inv;
                if (v.z > thrF) Y[row*(long)SPM_D + 4*i+2] = fmaxf(v.z - tau, 0.0f) * inv;
                if (v.w > thrF) Y[row*(long)SPM_D + 4*i+3] = fmaxf(v.w - tau, 0.0f) * inv;
            }
        }
    }
}

extern "C" void kernel_launch(void* const* d_in, const int* in_sizes, int n_in,
                              void* d_out, int out_size) {
    const float* X = (const float*)d_in[0];
    float* Y       = (float*)d_out;
    const int rows = in_sizes[0] / SPM_D;

    spm_kernel<<<rows, SPM_NT>>>(X, Y);
}

// round 12
// speedup vs baseline: 1.4207x; 1.1247x over previous
#include <cuda_runtime.h>
#include <cstddef>

// Sparsemax (alpha=2), read-once + zero-fill + register top-2 gather +
// sparse scatter.
// KEY FACT: every reference bisection iterate tau_m > rowmax-1, so every
// element x <= rowmax-1 yields EXACTLY 0 in the output (max(x-tau_m,0)=0 and
// 0/sum=0). Only the K ~ 8-30 candidates {x > rowmax-1} can be nonzero.
//   P1: single fused stream: read x (__ldcs) + write 0 to y (__stcs), while
//       each thread maintains the EXACT top-2 (v1,i1,v2) of its 100 elements
//       in registers (pure ALU, no syncs -> full MLP).
//   P2: thrF = rowmax-1. Threads with v1>thrF and v2<=thrF own exactly one
//       candidate -> pushed straight from registers (zero memory traffic).
//       Threads with v2>thrF (own >=2 candidates; expected ~0.3/row) re-read
//       their own 25 float4 and push everything > thrF.
//   tau: closed-form sorted-threshold rule for K<=32 (redundant per-warp),
//       warp-0 reference bisection for K<=FCAP, full-row bisection fallback.
//   P3: scatter the K nonzero outputs over the zero-filled row.

#define SPM_D   32000
#define SPM_D4  (SPM_D / 4)      // 8000 float4
#define SPM_NT  320
#define SPM_NW  (SPM_NT / 32)    // 10 warps
#define N_IT    25               // 8000 / 320 exact
#define FCAP    512

#define NEG_INF (-3.402823466e38f)
#define FULL    0xffffffffu

__device__ __forceinline__ float warp_max(float v) {
#pragma unroll
    for (int o = 16; o; o >>= 1) v = fmaxf(v, __shfl_xor_sync(FULL, v, o));
    return v;
}
__device__ __forceinline__ float warp_sum(float v) {
#pragma unroll
    for (int o = 16; o; o >>= 1) v += __shfl_xor_sync(FULL, v, o);
    return v;
}

__global__ __launch_bounds__(SPM_NT, 5)
void spm_kernel(const float* __restrict__ X, float* __restrict__ Y) {
    __shared__ float s_val[FCAP];
    __shared__ int   s_idx[FCAP];
    __shared__ float s_wmax[SPM_NW];
    __shared__ float s_r[SPM_NW];
    __shared__ int   s_K;
    __shared__ float s_tau, s_inv;

    const int tid  = threadIdx.x;
    const int lane = tid & 31;
    const int wid  = tid >> 5;
    const long row = blockIdx.x;

    const float4* __restrict__ x4 =
        reinterpret_cast<const float4*>(X + row * (long)SPM_D);
    float4* __restrict__ y4 =
        reinterpret_cast<float4*>(Y + row * (long)SPM_D);

    if (tid == 0) s_K = 0;

    // ---- P1: fused read-stream + zero-fill + exact per-thread top-2 ----
    const float4 zero4 = make_float4(0.0f, 0.0f, 0.0f, 0.0f);
    float v1 = NEG_INF, v2 = NEG_INF;   // top-2 of this thread's elements
    int   i1 = 0;                        // global index of v1
#pragma unroll 5
    for (int j = 0; j < N_IT; ++j) {
        const int i = j * SPM_NT + tid;
        float4 v = __ldcs(&x4[i]);
        __stcs(&y4[i], zero4);

        // top of the 4, with sub-index
        float m1, m3; int j1, j3;
        if (v.y > v.x) { m1 = v.y; j1 = 1; } else { m1 = v.x; j1 = 0; }
        if (v.w > v.z) { m3 = v.w; j3 = 3; } else { m3 = v.z; j3 = 2; }
        float top; int jt;
        if (m3 > m1) { top = m3; jt = j3; } else { top = m1; jt = j1; }

        if (top > v1) {
            // exact second of the 4
            float m2  = fminf(v.x, v.y), m4 = fminf(v.z, v.w);
            float sec = fmaxf(fminf(m1, m3), (m1 > m3) ? m2 : m4);
            v2 = fmaxf(v1, sec);
            v1 = top;
            i1 = 4 * i + jt;
        } else {
            v2 = fmaxf(v2, top);
        }
    }
    float mw = warp_max(v1);
    if (lane == 0) s_wmax[wid] = mw;
    __syncthreads();                           // barrier 1 (orders s_K too)

    float mm = (lane < SPM_NW) ? s_wmax[lane] : NEG_INF;
    const float mxv   = warp_max(mm);          // block max, redundant per warp
    const float thrF  = mxv - 1.0f;
    const float inv_d = 1.0f / (float)SPM_D;

    // ---- P2: push candidates (register path; rare multi-owner re-read) ----
    if (v1 > thrF) {
        if (v2 <= thrF) {
            // exactly one candidate in this thread: from registers
            int p = atomicAdd(&s_K, 1);
            if (p < FCAP) { s_val[p] = v1; s_idx[p] = i1; }
        } else {
            // >=2 candidates in this thread (expected ~0.3 threads per row)
#pragma unroll 5
            for (int j = 0; j < N_IT; ++j) {
                const int i = j * SPM_NT + tid;
                float4 v = __ldcg(&x4[i]);
                if (v.x > thrF) { int p = atomicAdd(&s_K, 1); if (p < FCAP) { s_val[p] = v.x; s_idx[p] = 4*i+0; } }
                if (v.y > thrF) { int p = atomicAdd(&s_K, 1); if (p < FCAP) { s_val[p] = v.y; s_idx[p] = 4*i+1; } }
                if (v.z > thrF) { int p = atomicAdd(&s_K, 1); if (p < FCAP) { s_val[p] = v.z; s_idx[p] = 4*i+2; } }
                if (v.w > thrF) { int p = atomicAdd(&s_K, 1); if (p < FCAP) { s_val[p] = v.w; s_idx[p] = 4*i+3; } }
            }
        }
    }
    __syncthreads();                           // barrier 2
    const int K = s_K;                         // uniform; K >= 1 always

    float tau = 0.0f, inv = 1.0f;

    if (K <= 32) {
        // ---- Closed-form threshold, redundant per-warp (no barrier) ----
        float z = (lane < K) ? s_val[lane] : NEG_INF;
        // bitonic sort, descending
#pragma unroll
        for (int kk = 2; kk <= 32; kk <<= 1) {
#pragma unroll
            for (int j = kk >> 1; j > 0; j >>= 1) {
                float o = __shfl_xor_sync(FULL, z, j);
                bool lower   = (lane & j) == 0;
                bool descBlk = (lane & kk) == 0;
                z = (lower == descBlk) ? fmaxf(z, o) : fminf(z, o);
            }
        }
        // inclusive prefix sum
        float S = z;
#pragma unroll
        for (int o = 1; o < 32; o <<= 1) {
            float t = __shfl_up_sync(FULL, S, o);
            if (lane >= o) S += t;
        }
        float kf = (float)(lane + 1);
        unsigned bal = __ballot_sync(FULL, fmaf(kf, z, 1.0f) > S);
        int h = 31 - __clz(bal);               // lane 0 always qualifies
        tau = __shfl_sync(FULL, (S - 1.0f) / kf, h);
        float s = warp_sum(fmaxf(z - tau, 0.0f));
        inv = 1.0f / s;

        // ---- P3: sparse scatter of the K nonzero outputs ----
        if (tid < K)
            Y[row * (long)SPM_D + s_idx[tid]] =
                fmaxf(s_val[tid] - tau, 0.0f) * inv;
    } else if (K <= FCAP) {
        // ---- Reference bisection over candidates (warp 0) ----
        if (wid == 0) {
            float tlo = thrF;
            float dm  = (mxv - inv_d) - tlo;
            float a = 0.0f;
            for (int i = lane; i < K; i += 32)
                a += fmaxf(s_val[i] - tlo, 0.0f);
            const float flo = warp_sum(a) - 1.0f;
            float tm = tlo, fm = flo;
            for (int it = 0; it < 50; ++it) {
                dm *= 0.5f;
                tm = tlo + dm;
                float s = 0.0f;
                for (int i = lane; i < K; i += 32)
                    s += fmaxf(s_val[i] - tm, 0.0f);
                fm = warp_sum(s) - 1.0f;
                if (fm * flo >= 0.0f) tlo = tm;
            }
            if (lane == 0) { s_tau = tm; s_inv = 1.0f / (fm + 1.0f); }
        }
        __syncthreads();
        tau = s_tau; inv = s_inv;

        for (int p = tid; p < K; p += SPM_NT)
            Y[row * (long)SPM_D + s_idx[p]] =
                fmaxf(s_val[p] - tau, 0.0f) * inv;
    } else {
        // ---- Overflow fallback (correctness only): full-row bisection ----
        float tlo = thrF;
        float dm  = (mxv - inv_d) - tlo;

        float a = 0.0f;
        for (int i = tid; i < SPM_D4; i += SPM_NT) {
            float4 v = __ldcg(&x4[i]);
            a += fmaxf(v.x - tlo, 0.0f) + fmaxf(v.y - tlo, 0.0f) +
                 fmaxf(v.z - tlo, 0.0f) + fmaxf(v.w - tlo, 0.0f);
        }
        a = warp_sum(a);
        if (lane == 0) s_r[wid] = a;
        __syncthreads();
        float r0 = (lane < SPM_NW) ? s_r[lane] : 0.0f;
        const float flo = warp_sum(r0) - 1.0f;

        float tm = tlo, fm = flo;
        for (int it = 0; it < 50; ++it) {
            dm *= 0.5f;
            tm = tlo + dm;
            float s = 0.0f;
            for (int i = tid; i < SPM_D4; i += SPM_NT) {
                float4 v = __ldcg(&x4[i]);
                s += fmaxf(v.x - tm, 0.0f) + fmaxf(v.y - tm, 0.0f) +
                     fmaxf(v.z - tm, 0.0f) + fmaxf(v.w - tm, 0.0f);
            }
            s = warp_sum(s);
            __syncthreads();
            if (lane == 0) s_r[wid] = s;
            __syncthreads();
            float rr = (lane < SPM_NW) ? s_r[lane] : 0.0f;
            fm = warp_sum(rr) - 1.0f;
            if (fm * flo >= 0.0f) tlo = tm;
        }
        tau = tm;
        inv = 1.0f / (fm + 1.0f);

        // scatter: rescan and write elements above thrF
        // (elements in (thrF, tau] write 0 over 0 -- harmless)
        if (v1 > thrF) {
#pragma unroll 5
            for (int j = 0; j < N_IT; ++j) {
                const int i = j * SPM_NT + tid;
                float4 v = __ldcg(&x4[i]);
                if (v.x > thrF) Y[row*(long)SPM_D + 4*i+0] = fmaxf(v.x - tau, 0.0f) * inv;
                if (v.y > thrF) Y[row*(long)SPM_D + 4*i+1] = fmaxf(v.y - tau, 0.0f) * inv;
                if (v.z > thrF) Y[row*(long)SPM_D + 4*i+2] = fmaxf(v.z - tau, 0.0f) * inv;
                if (v.w > thrF) Y[row*(long)SPM_D + 4*i+3] = fmaxf(v.w - tau, 0.0f) * inv;
            }
        }
    }
}

extern "C" void kernel_launch(void* const* d_in, const int* in_sizes, int n_in,
                              void* d_out, int out_size) {
    const float* X = (const float*)d_in[0];
    float* Y       = (float*)d_out;
    const int rows = in_sizes[0] / SPM_D;

    spm_kernel<<<rows, SPM_NT>>>(X, Y);
}